// round 16
// baseline (speedup 1.0000x reference)
#include <cuda_runtime.h>
#include <cstdint>

// PeakAligner: L=220, window=[57,87); start=index_max-57 in [0,29]
//   in_bounds <=> start<=28; ss=min(start,28)
//   valid <=> r[ss+57]==max(r[ss..ss+191]) && max(r[ss..ss+56]) < that max && in_bounds
//   downsample: r[ss+3*i], i=0..63
//
// Champion memory schedule (depth-2, distance-1 cp.async pipeline) with
// 16-warp blocks: half the barrier crossings per row, 14 KB prefetch bursts.

#define L_DIM 220
#define WIN_LO 57
#define WIN_LEN 30
#define MAX_START 28
#define ROWS_PER_TILE 16
#define TILES_PER_BLOCK 4
#define THREADS 512
#define FLOATS_PER_TILE (ROWS_PER_TILE * L_DIM)   // 3520

__device__ __forceinline__ unsigned ford(float f) {
    unsigned u = __float_as_uint(f);
    return u ^ (unsigned)(((int)u >> 31) | 0x80000000);
}
__device__ __forceinline__ float unford(unsigned t) {
    unsigned u = (t & 0x80000000u) ? (t ^ 0x80000000u) : ~t;
    return __uint_as_float(u);
}

__device__ __forceinline__ void prefetch_tile(float* sbuf, const float* __restrict__ in,
                                              long long row0, int rows_here) {
    const float4* gin = reinterpret_cast<const float4*>(in + row0 * L_DIM);
    const int total4 = rows_here * (L_DIM / 4);               // up to 880
    int i = threadIdx.x;
    if (i < total4) {
        uint32_t sa = (uint32_t)__cvta_generic_to_shared(reinterpret_cast<float4*>(sbuf) + i);
        asm volatile("cp.async.cg.shared.global [%0], [%1], 16;\n" :: "r"(sa), "l"(gin + i));
    }
    i += THREADS;
    if (i < total4) {
        uint32_t sa = (uint32_t)__cvta_generic_to_shared(reinterpret_cast<float4*>(sbuf) + i);
        asm volatile("cp.async.cg.shared.global [%0], [%1], 16;\n" :: "r"(sa), "l"(gin + i));
    }
    asm volatile("cp.async.commit_group;\n");
}

__global__ __launch_bounds__(THREADS)
void peak_aligner_kernel(const float* __restrict__ in,
                         float* __restrict__ out,
                         float* __restrict__ mask_out,
                         int K, int total_tiles) {
    __shared__ float s[2][FLOATS_PER_TILE];       // 28160 B -> 4 blocks/SM (64 warps)

    const int w    = threadIdx.x >> 5;            // 0..15
    const int lane = threadIdx.x & 31;

    int tile = blockIdx.x * TILES_PER_BLOCK;
    if (tile >= total_tiles) return;
    const int T = min(TILES_PER_BLOCK, total_tiles - tile);

    // prime the pipeline
    {
        const long long r0 = (long long)tile * ROWS_PER_TILE;
        prefetch_tile(s[0], in, r0, min(ROWS_PER_TILE, K - (int)r0));
    }

    #pragma unroll 1
    for (int t = 0; t < T; t++, tile++) {
        if (t + 1 < T) {
            const long long r0n = (long long)(tile + 1) * ROWS_PER_TILE;
            prefetch_tile(s[(t + 1) & 1], in, r0n, min(ROWS_PER_TILE, K - (int)r0n));
            asm volatile("cp.async.wait_group 1;\n" ::: "memory");
        } else {
            asm volatile("cp.async.wait_group 0;\n" ::: "memory");
        }
        __syncthreads();

        const int row0 = tile * ROWS_PER_TILE;
        const int rows_here = min(ROWS_PER_TILE, K - row0);
        if (w < rows_here) {
            const float* r = s[t & 1] + w * L_DIM;
            const int row = row0 + w;

            // Step 1: first-argmax over window [57,87)
            const unsigned wu = (lane < WIN_LEN) ? ford(r[WIN_LO + lane]) : 0u;
            const unsigned wmax = __reduce_max_sync(0xffffffffu, wu);
            const unsigned wb = __ballot_sync(0xffffffffu, wu == wmax);
            const int start = __ffs(wb) - 1;
            const bool in_bounds = (start <= MAX_START);
            const int ss = min(start, MAX_START);

            // Step 2: valid <=> v57==M(0..191) && P(0..56)<M
            const float* p = r + ss;
            const float x0 = p[lane];
            const float x1 = p[lane + 32];
            const float x2 = p[lane + 64];
            const float x3 = p[lane + 96];
            const float x4 = p[lane + 128];
            const float x5 = p[lane + 160];
            const float Ml = fmaxf(fmaxf(fmaxf(x0, x1), fmaxf(x2, x3)), fmaxf(x4, x5));
            const float Pl = (lane < 25) ? fmaxf(x0, x1) : x0;
            const float M = unford(__reduce_max_sync(0xffffffffu, ford(Ml)));
            const float P = unford(__reduce_max_sync(0xffffffffu, ford(Pl)));
            const float v57 = p[57];
            const bool valid = (v57 == M) && (P < M) && in_bounds;

            // Step 3: downsample + mask (streaming stores)
            const float o0 = valid ? p[3 * lane]      : 0.0f;
            const float o1 = valid ? p[3 * lane + 96] : 0.0f;
            float* orow = out + (size_t)row * 64;
            __stcs(orow + lane,      o0);
            __stcs(orow + lane + 32, o1);
            if (lane == 0)
                __stcs(mask_out + row, valid ? 0.0f : 1.0f);
        }
        __syncthreads();   // all warps done with s[t&1] before it is refilled
    }
}

extern "C" void kernel_launch(void* const* d_in, const int* in_sizes, int n_in,
                              void* d_out, int out_size) {
    const float* in = (const float*)d_in[0];
    const int K = in_sizes[0] / L_DIM;
    float* out  = (float*)d_out;
    float* mask = out + (size_t)K * 64;
    const int total_tiles = (K + ROWS_PER_TILE - 1) / ROWS_PER_TILE;
    const int blocks = (total_tiles + TILES_PER_BLOCK - 1) / TILES_PER_BLOCK;
    peak_aligner_kernel<<<blocks, THREADS>>>(in, out, mask, K, total_tiles);
}

// round 17
// speedup vs baseline: 1.0080x; 1.0080x over previous
#include <cuda_runtime.h>
#include <cstdint>

// PeakAligner: L=220, window=[57,87); start=index_max-57 in [0,29]
//   in_bounds <=> start<=28; ss=min(start,28)
//   valid <=> r[ss+57]==max(r[ss..ss+191]) && max(r[ss..ss+56]) < that max && in_bounds
//   downsample: r[ss+3*i], i=0..63
//
// FINAL CHAMPION: block-cooperative cp.async smem pipeline, 8 rows/tile,
// 4 tiles/block, double-buffered, prefetch distance 1.
// Best measured: 84.03 us bench / 79.52 us ncu, DRAM 87.0%, 6.89 TB/s.

#define L_DIM 220
#define WIN_LO 57
#define WIN_LEN 30
#define MAX_START 28
#define ROWS_PER_TILE 8
#define TILES_PER_BLOCK 4
#define THREADS 256
#define FLOATS_PER_TILE (ROWS_PER_TILE * L_DIM)   // 1760

__device__ __forceinline__ unsigned ford(float f) {
    unsigned u = __float_as_uint(f);
    return u ^ (unsigned)(((int)u >> 31) | 0x80000000);
}
__device__ __forceinline__ float unford(unsigned t) {
    unsigned u = (t & 0x80000000u) ? (t ^ 0x80000000u) : ~t;
    return __uint_as_float(u);
}

__device__ __forceinline__ void prefetch_tile(float* sbuf, const float* __restrict__ in,
                                              long long row0, int rows_here) {
    const float4* gin = reinterpret_cast<const float4*>(in + row0 * L_DIM);
    const int total4 = rows_here * (L_DIM / 4);
    int i = threadIdx.x;
    if (i < total4) {
        uint32_t sa = (uint32_t)__cvta_generic_to_shared(reinterpret_cast<float4*>(sbuf) + i);
        asm volatile("cp.async.cg.shared.global [%0], [%1], 16;\n" :: "r"(sa), "l"(gin + i));
    }
    i += THREADS;
    if (i < total4) {
        uint32_t sa = (uint32_t)__cvta_generic_to_shared(reinterpret_cast<float4*>(sbuf) + i);
        asm volatile("cp.async.cg.shared.global [%0], [%1], 16;\n" :: "r"(sa), "l"(gin + i));
    }
    asm volatile("cp.async.commit_group;\n");
}

__global__ __launch_bounds__(THREADS)
void peak_aligner_kernel(const float* __restrict__ in,
                         float* __restrict__ out,
                         float* __restrict__ mask_out,
                         int K, int total_tiles) {
    __shared__ float s[2][FLOATS_PER_TILE];

    const int w    = threadIdx.x >> 5;
    const int lane = threadIdx.x & 31;

    int tile = blockIdx.x * TILES_PER_BLOCK;
    if (tile >= total_tiles) return;
    const int T = min(TILES_PER_BLOCK, total_tiles - tile);

    // prime the pipeline
    {
        const long long r0 = (long long)tile * ROWS_PER_TILE;
        prefetch_tile(s[0], in, r0, min(ROWS_PER_TILE, K - (int)r0));
    }

    #pragma unroll 1
    for (int t = 0; t < T; t++, tile++) {
        const bool have_next = (t + 1 < T);
        if (have_next) {
            const long long r0n = (long long)(tile + 1) * ROWS_PER_TILE;
            prefetch_tile(s[(t + 1) & 1], in, r0n, min(ROWS_PER_TILE, K - (int)r0n));
            asm volatile("cp.async.wait_group 1;\n" ::: "memory");
        } else {
            asm volatile("cp.async.wait_group 0;\n" ::: "memory");
        }
        __syncthreads();

        const int row0 = tile * ROWS_PER_TILE;
        const int rows_here = min(ROWS_PER_TILE, K - row0);
        if (w < rows_here) {
            const float* r = s[t & 1] + w * L_DIM;
            const int row = row0 + w;

            // Step 1: first-argmax over window [57,87)
            const unsigned wu = (lane < WIN_LEN) ? ford(r[WIN_LO + lane]) : 0u;
            const unsigned wmax = __reduce_max_sync(0xffffffffu, wu);
            const unsigned wb = __ballot_sync(0xffffffffu, wu == wmax);
            const int start = __ffs(wb) - 1;
            const bool in_bounds = (start <= MAX_START);
            const int ss = min(start, MAX_START);

            // Step 2: valid <=> v57==M(0..191) && P(0..56)<M
            const float* p = r + ss;
            const float x0 = p[lane];
            const float x1 = p[lane + 32];
            const float x2 = p[lane + 64];
            const float x3 = p[lane + 96];
            const float x4 = p[lane + 128];
            const float x5 = p[lane + 160];
            const float Ml = fmaxf(fmaxf(fmaxf(x0, x1), fmaxf(x2, x3)), fmaxf(x4, x5));
            const float Pl = (lane < 25) ? fmaxf(x0, x1) : x0;
            const float M = unford(__reduce_max_sync(0xffffffffu, ford(Ml)));
            const float P = unford(__reduce_max_sync(0xffffffffu, ford(Pl)));
            const float v57 = p[57];
            const bool valid = (v57 == M) && (P < M) && in_bounds;

            // Step 3: downsample + mask (streaming stores)
            const float o0 = valid ? p[3 * lane]      : 0.0f;
            const float o1 = valid ? p[3 * lane + 96] : 0.0f;
            float* orow = out + (size_t)row * 64;
            __stcs(orow + lane,      o0);
            __stcs(orow + lane + 32, o1);
            if (lane == 0)
                __stcs(mask_out + row, valid ? 0.0f : 1.0f);
        }
        __syncthreads();   // all warps done with s[t&1] before it is refilled
    }
}

extern "C" void kernel_launch(void* const* d_in, const int* in_sizes, int n_in,
                              void* d_out, int out_size) {
    const float* in = (const float*)d_in[0];
    const int K = in_sizes[0] / L_DIM;
    float* out  = (float*)d_out;
    float* mask = out + (size_t)K * 64;
    const int total_tiles = (K + ROWS_PER_TILE - 1) / ROWS_PER_TILE;
    const int blocks = (total_tiles + TILES_PER_BLOCK - 1) / TILES_PER_BLOCK;
    peak_aligner_kernel<<<blocks, THREADS>>>(in, out, mask, K, total_tiles);
}